// round 16
// baseline (speedup 1.0000x reference)
#include <cuda_runtime.h>
#include <cuda_fp16.h>

#define Bn 4
#define Ln 2048
#define Dn 1024
#define Hn 16
#define BLn (Bn*Ln)   // 8192
#define BHn (Bn*Hn)   // 64

__device__ __half g_xh[3][(size_t)BLn*Dn];
__device__ __half g_wt[4][(size_t)Dn*Dn];      // W^T [n][k]
__device__ unsigned g_mbits[(size_t)Bn*Ln*64];
__device__ __half g_qh[(size_t)BHn*Ln*64];
__device__ __half g_kh[(size_t)BHn*Ln*64];
__device__ __half g_vt[(size_t)BHn*64*Ln];     // V^T [bh][d][l]
__device__ __half g_oh[(size_t)BHn*Ln*64];
__device__ __half g_ps[(size_t)BHn*Ln*Ln];     // unnormalized P [bh][l][Ln]

// ---------------------------------------------------------------------------
__device__ __forceinline__ void hmma(float d[4], const unsigned a[4], const unsigned b[2]) {
    asm volatile(
        "mma.sync.aligned.m16n8k16.row.col.f32.f16.f16.f32 "
        "{%0,%1,%2,%3}, {%4,%5,%6,%7}, {%8,%9}, {%0,%1,%2,%3};"
        : "+f"(d[0]), "+f"(d[1]), "+f"(d[2]), "+f"(d[3])
        : "r"(a[0]), "r"(a[1]), "r"(a[2]), "r"(a[3]), "r"(b[0]), "r"(b[1]));
}

__device__ __forceinline__ void ldm4(unsigned r[4], const __half* p) {
    unsigned addr = (unsigned)__cvta_generic_to_shared(p);
    asm volatile("ldmatrix.sync.aligned.m8n8.x4.shared.b16 {%0,%1,%2,%3}, [%4];"
        : "=r"(r[0]), "=r"(r[1]), "=r"(r[2]), "=r"(r[3]) : "r"(addr));
}
__device__ __forceinline__ void ldmA(unsigned r[4], const __half* base, int ldw,
                                     int rb, int kk, int lane) {
    ldm4(r, base + (size_t)(rb + (lane & 15)) * ldw + kk + ((lane >> 4) << 3));
}
__device__ __forceinline__ void ldmB2(unsigned r[4], const __half* base, int ldw,
                                      int nb, int kk, int lane) {
    ldm4(r, base + (size_t)(nb + (lane & 7) + ((lane & 16) >> 1)) * ldw
            + kk + ((lane & 8) ? 8 : 0));
}

__device__ __forceinline__ void cp16(void* s, const void* g) {
    unsigned sa = (unsigned)__cvta_generic_to_shared(s);
    asm volatile("cp.async.cg.shared.global [%0], [%1], 16;" :: "r"(sa), "l"(g));
}
#define CP_COMMIT() asm volatile("cp.async.commit_group;")
#define CP_WAIT0()  asm volatile("cp.async.wait_group 0;")

__device__ __forceinline__ void stcs4(float* p, float4 v) {
    asm volatile("st.global.cs.v4.f32 [%0], {%1,%2,%3,%4};"
        :: "l"(p), "f"(v.x), "f"(v.y), "f"(v.z), "f"(v.w));
}

// ---------------------------------------------------------------------------
// pack kernels
// ---------------------------------------------------------------------------
__global__ __launch_bounds__(256) void pack_x_kernel(
    const float* __restrict__ q, const float* __restrict__ k, const float* __restrict__ v)
{
    int z = blockIdx.y;
    const float* src = (z == 0) ? q : (z == 1) ? k : v;
    __half* dst = g_xh[z];
    size_t i = (size_t)blockIdx.x * 256 + threadIdx.x;
    float4 a = ((const float4*)src)[i];
    ((__half2*)dst)[2 * i]     = __floats2half2_rn(a.x, a.y);
    ((__half2*)dst)[2 * i + 1] = __floats2half2_rn(a.z, a.w);
}

__global__ void pack_w_kernel(
    const float* __restrict__ Wq, const float* __restrict__ Wk,
    const float* __restrict__ Wv, const float* __restrict__ Wo)
{
    __shared__ float s[32][33];
    int z = blockIdx.z;
    const float* W = (z == 0) ? Wq : (z == 1) ? Wk : (z == 2) ? Wv : Wo;
    __half* dst = g_wt[z];
    int k0 = blockIdx.x * 32, n0 = blockIdx.y * 32;
    int tx = threadIdx.x, ty = threadIdx.y;
#pragma unroll
    for (int i = 0; i < 4; i++)
        s[ty + 8 * i][tx] = W[(size_t)(k0 + ty + 8 * i) * 1024 + n0 + tx];
    __syncthreads();
#pragma unroll
    for (int i = 0; i < 4; i++)
        dst[(size_t)(n0 + ty + 8 * i) * 1024 + k0 + tx] = __float2half(s[tx][ty + 8 * i]);
}

__global__ __launch_bounds__(256) void pack_mask_kernel(const int* __restrict__ mask)
{
    size_t i = (size_t)blockIdx.x * 256 + threadIdx.x;
    int m = mask[i];
    unsigned w = __ballot_sync(~0u, m != 0);
    if ((threadIdx.x & 31) == 0) g_mbits[i >> 5] = w;
}

// ---------------------------------------------------------------------------
// QKV projection: BK=64, 2-stage cp.async, ldmatrix; V written transposed.
// (round-12 configuration)
// ---------------------------------------------------------------------------
#define LDW 72
#define PROJ_SMEM_BYTES (4 * 128 * LDW * 2)

__global__ __launch_bounds__(256) void proj_qkv_kernel(
    const float* __restrict__ bq, const float* __restrict__ bk, const float* __restrict__ bv)
{
    const int z = blockIdx.z;
    const __half* A  = g_xh[z];
    const __half* Wt = g_wt[z];
    const float* bias = (z == 0) ? bq : (z == 1) ? bk : bv;

    extern __shared__ __half dsm[];
    __half* As = dsm;
    __half* Ws = dsm + 2 * 128 * LDW;

    const int tid  = threadIdx.x;
    const int lane = tid & 31;
    const int warp = tid >> 5;
    const int g    = lane >> 2;
    const int tig  = lane & 3;
    const int wm   = warp & 3;
    const int wn   = warp >> 2;
    const int m0   = blockIdx.y * 128;
    const int n0   = blockIdx.x * 128;

    float acc[2][8][4];
#pragma unroll
    for (int mt = 0; mt < 2; mt++)
#pragma unroll
        for (int nt = 0; nt < 8; nt++)
#pragma unroll
            for (int e = 0; e < 4; e++) acc[mt][nt][e] = 0.f;

    auto loadStage = [&](int kn, int st) {
        __half* Ad = As + st * 128 * LDW;
        __half* Wd = Ws + st * 128 * LDW;
#pragma unroll
        for (int i = 0; i < 4; i++) {
            int id = tid + i * 256;
            int r = id >> 3, c = (id & 7) * 8;
            cp16(&Ad[r * LDW + c], &A[(size_t)(m0 + r) * 1024 + kn + c]);
            cp16(&Wd[r * LDW + c], &Wt[(size_t)(n0 + r) * 1024 + kn + c]);
        }
    };

    loadStage(0, 0);
    CP_COMMIT();

    for (int it = 0; it < 16; it++) {
        CP_WAIT0();
        __syncthreads();
        if (it + 1 < 16) {
            loadStage((it + 1) * 64, (it + 1) & 1);
            CP_COMMIT();
        }
        const __half* Ac = As + (it & 1) * 128 * LDW;
        const __half* Wc = Ws + (it & 1) * 128 * LDW;
#pragma unroll
        for (int ks = 0; ks < 4; ks++) {
            const int kk = ks * 16;
            unsigned af[2][4], bf[8][2];
#pragma unroll
            for (int mt = 0; mt < 2; mt++)
                ldmA(af[mt], Ac, LDW, wm * 32 + mt * 16, kk, lane);
#pragma unroll
            for (int np = 0; np < 4; np++) {
                unsigned t[4];
                ldmB2(t, Wc, LDW, wn * 64 + np * 16, kk, lane);
                bf[np * 2][0] = t[0]; bf[np * 2][1] = t[1];
                bf[np * 2 + 1][0] = t[2]; bf[np * 2 + 1][1] = t[3];
            }
#pragma unroll
            for (int mt = 0; mt < 2; mt++)
#pragma unroll
                for (int nt = 0; nt < 8; nt++) hmma(acc[mt][nt], af[mt], bf[nt]);
        }
        __syncthreads();
    }

    if (z == 2) {
#pragma unroll
        for (int mt = 0; mt < 2; mt++) {
            int rb = wm * 32 + mt * 16;
#pragma unroll
            for (int nt = 0; nt < 8; nt++) {
                int gn = n0 + wn * 64 + nt * 8 + 2 * tig;
                int h = gn >> 6, d = gn & 63;
                float b0v = bias[gn], b1v = bias[gn + 1];
#pragma unroll
                for (int hh = 0; hh < 2; hh++) {
                    int gm = m0 + rb + hh * 8 + g;
                    int bb_ = gm >> 11, l = gm & 2047;
                    __half* vt = g_vt + (size_t)(bb_ * Hn + h) * 64 * Ln;
                    vt[(size_t)d * Ln + l]       = __float2half(acc[mt][nt][hh * 2 + 0] + b0v);
                    vt[(size_t)(d + 1) * Ln + l] = __float2half(acc[mt][nt][hh * 2 + 1] + b1v);
                }
            }
        }
    } else {
        __half* dst = (z == 0) ? g_qh : g_kh;
#pragma unroll
        for (int mt = 0; mt < 2; mt++) {
            int rb = wm * 32 + mt * 16;
#pragma unroll
            for (int nt = 0; nt < 8; nt++) {
                int gn = n0 + wn * 64 + nt * 8 + 2 * tig;
                int h = gn >> 6, d = gn & 63;
                float b0v = bias[gn], b1v = bias[gn + 1];
#pragma unroll
                for (int hh = 0; hh < 2; hh++) {
                    int gm = m0 + rb + hh * 8 + g;
                    int bb_ = gm >> 11, l = gm & 2047;
                    __half2 o = __floats2half2_rn(acc[mt][nt][hh * 2 + 0] + b0v,
                                                  acc[mt][nt][hh * 2 + 1] + b1v);
                    *(__half2*)&dst[(size_t)((bb_ * Hn + h) * Ln + l) * 64 + d] = o;
                }
            }
        }
    }
}

// ---------------------------------------------------------------------------
// Output projection: BK=64, 2-stage cp.async, ldmatrix
// ---------------------------------------------------------------------------
__global__ __launch_bounds__(256) void out_proj_kernel(
    const float* __restrict__ bo, float* __restrict__ out)
{
    const __half* Wt = g_wt[3];
    extern __shared__ __half dsm[];
    __half* As = dsm;
    __half* Ws = dsm + 2 * 128 * LDW;

    const int tid  = threadIdx.x;
    const int lane = tid & 31;
    const int warp = tid >> 5;
    const int g    = lane >> 2;
    const int tig  = lane & 3;
    const int wm   = warp & 3;
    const int wn   = warp >> 2;
    const int m0   = blockIdx.y * 128;
    const int n0   = blockIdx.x * 128;

    float acc[2][8][4];
#pragma unroll
    for (int mt = 0; mt < 2; mt++)
#pragma unroll
        for (int nt = 0; nt < 8; nt++)
#pragma unroll
            for (int e = 0; e < 4; e++) acc[mt][nt][e] = 0.f;

    auto loadStage = [&](int kn, int st) {
        __half* Ad = As + st * 128 * LDW;
        __half* Wd = Ws + st * 128 * LDW;
#pragma unroll
        for (int i = 0; i < 4; i++) {
            int id = tid + i * 256;
            int r = id >> 3, c = (id & 7) * 8;
            int gr = m0 + r;
            int bb_ = gr >> 11, l = gr & 2047;
            int kk = kn + c;
            int h = kk >> 6, dv = kk & 63;
            cp16(&Ad[r * LDW + c], &g_oh[(size_t)((bb_ * Hn + h) * Ln + l) * 64 + dv]);
            cp16(&Wd[r * LDW + c], &Wt[(size_t)(n0 + r) * 1024 + kn + c]);
        }
    };

    loadStage(0, 0);
    CP_COMMIT();

    for (int it = 0; it < 16; it++) {
        CP_WAIT0();
        __syncthreads();
        if (it + 1 < 16) {
            loadStage((it + 1) * 64, (it + 1) & 1);
            CP_COMMIT();
        }
        const __half* Ac = As + (it & 1) * 128 * LDW;
        const __half* Wc = Ws + (it & 1) * 128 * LDW;
#pragma unroll
        for (int ks = 0; ks < 4; ks++) {
            const int kk = ks * 16;
            unsigned af[2][4], bf[8][2];
#pragma unroll
            for (int mt = 0; mt < 2; mt++)
                ldmA(af[mt], Ac, LDW, wm * 32 + mt * 16, kk, lane);
#pragma unroll
            for (int np = 0; np < 4; np++) {
                unsigned t[4];
                ldmB2(t, Wc, LDW, wn * 64 + np * 16, kk, lane);
                bf[np * 2][0] = t[0]; bf[np * 2][1] = t[1];
                bf[np * 2 + 1][0] = t[2]; bf[np * 2 + 1][1] = t[3];
            }
#pragma unroll
            for (int mt = 0; mt < 2; mt++)
#pragma unroll
                for (int nt = 0; nt < 8; nt++) hmma(acc[mt][nt], af[mt], bf[nt]);
        }
        __syncthreads();
    }
#pragma unroll
    for (int mt = 0; mt < 2; mt++) {
        int rb = wm * 32 + mt * 16;
#pragma unroll
        for (int nt = 0; nt < 8; nt++) {
            int gn = n0 + wn * 64 + nt * 8 + 2 * tig;
            float b0v = bo[gn], b1v = bo[gn + 1];
#pragma unroll
            for (int hh = 0; hh < 2; hh++) {
                int gm = m0 + rb + hh * 8 + g;
                float2 o;
                o.x = acc[mt][nt][hh * 2 + 0] + b0v;
                o.y = acc[mt][nt][hh * 2 + 1] + b1v;
                *(float2*)&out[(size_t)gm * 1024 + gn] = o;
            }
        }
    }
}

// ---------------------------------------------------------------------------
// Fused attention (round-12 config; phase-2: PV mma issued before attn write,
// redundant trailing barrier removed)
// ---------------------------------------------------------------------------
#define LDQ 72
#define LDK 72
#define LDP 136
#define LDV 136
#define UNION_HALVES (2 * 128 * LDP + 2 * 64 * LDV)
#define ATTN_SMEM_BYTES ((256 + 128) * 4 + UNION_HALVES * 2)

__global__ __launch_bounds__(256, 2) void attn_fused_kernel(
    float* __restrict__ attn_out)
{
    extern __shared__ char smraw[];
    float* part = (float*)smraw;            // [2][128]
    float* invs = part + 256;               // [128]
    __half* U   = (__half*)(invs + 128);
    // phase 1 aliases
    __half* Qs  = U;
    __half* Ks0 = U + 128 * LDQ;
    __half* Ks1 = Ks0 + 128 * LDK;
    // phase 2 aliases
    __half* Ps0 = U;
    __half* Ps1 = Ps0 + 128 * LDP;
    __half* Vs0 = Ps1 + 128 * LDP;
    __half* Vs1 = Vs0 + 64 * LDV;

    const int tid  = threadIdx.x;
    const int lane = tid & 31;
    const int warp = tid >> 5;
    const int g    = lane >> 2;
    const int tig  = lane & 3;
    const int wm   = warp & 3;
    const int wn   = warp >> 2;

    const int q0 = blockIdx.x * 128;
    const int h  = blockIdx.y;
    const int b  = blockIdx.z;
    const int bh = b * Hn + h;
    const __half* Qh = g_qh + (size_t)bh * Ln * 64;
    const __half* Kh = g_kh + (size_t)bh * Ln * 64;
    const __half* Vt = g_vt + (size_t)bh * 64 * Ln;
    const unsigned* mb = g_mbits + (size_t)b * Ln * 64;
    __half* Pb = g_ps + (size_t)bh * Ln * Ln;

    auto loadK = [&](int j0, __half* dstK) {
#pragma unroll
        for (int i = 0; i < 4; i++) {
            int id = tid + i * 256;
            int r = id >> 3, c = (id & 7) * 8;
            cp16(&dstK[r * LDK + c], &Kh[(size_t)(j0 + r) * 64 + c]);
        }
    };

    // ======================= PHASE 1: QK -> P, rowsums =======================
#pragma unroll
    for (int i = 0; i < 4; i++) {
        int id = tid + i * 256;
        int r = id >> 3, c8 = id & 7;
        *(uint4*)&Qs[r * LDQ + c8 * 8] = *(const uint4*)&Qh[(size_t)(q0 + r) * 64 + c8 * 8];
    }

    float rsum[2][2] = {{0.f, 0.f}, {0.f, 0.f}};
    loadK(0, Ks0);
    CP_COMMIT();
    __syncthreads();

    for (int jc = 0; jc < 16; jc++) {
        const int j0 = jc * 128;
        CP_WAIT0();
        __syncthreads();
        if (jc + 1 < 16) {
            loadK((jc + 1) * 128, (jc & 1) ? Ks0 : Ks1);
            CP_COMMIT();
        }
        const __half* Kc = (jc & 1) ? Ks1 : Ks0;

        float acc[2][8][4];
#pragma unroll
        for (int mt = 0; mt < 2; mt++)
#pragma unroll
            for (int nt = 0; nt < 8; nt++)
#pragma unroll
                for (int e = 0; e < 4; e++) acc[mt][nt][e] = 0.f;
#pragma unroll
        for (int ks = 0; ks < 4; ks++) {
            const int kk = ks * 16;
            unsigned af[2][4], bf[8][2];
#pragma unroll
            for (int mt = 0; mt < 2; mt++)
                ldmA(af[mt], Qs, LDQ, wm * 32 + mt * 16, kk, lane);
#pragma unroll
            for (int np = 0; np < 4; np++) {
                unsigned t[4];
                ldmB2(t, Kc, LDK, wn * 64 + np * 16, kk, lane);
                bf[np * 2][0] = t[0]; bf[np * 2][1] = t[1];
                bf[np * 2 + 1][0] = t[2]; bf[np * 2 + 1][1] = t[3];
            }
#pragma unroll
            for (int mt = 0; mt < 2; mt++)
#pragma unroll
                for (int nt = 0; nt < 8; nt++) hmma(acc[mt][nt], af[mt], bf[nt]);
        }

#pragma unroll
        for (int mt = 0; mt < 2; mt++) {
            int rb = wm * 32 + mt * 16;
            int r0g = q0 + rb + g;
            int r1g = r0g + 8;
            uint2 w0 = *(const uint2*)&mb[(size_t)r0g * 64 + jc * 4 + wn * 2];
            uint2 w1 = *(const uint2*)&mb[(size_t)r1g * 64 + jc * 4 + wn * 2];
            __half* p0p = Pb + (size_t)r0g * Ln + j0;
            __half* p1p = Pb + (size_t)r1g * Ln + j0;
#pragma unroll
            for (int nt = 0; nt < 8; nt++) {
                int c   = wn * 64 + nt * 8 + 2 * tig;
                int cb  = nt * 8 + 2 * tig;
                int bit = cb & 31;
                unsigned m0w = (cb >> 5) ? w0.y : w0.x;
                unsigned m1w = (cb >> 5) ? w1.y : w1.x;
                float p0 = ((m0w >> bit) & 1u)       ? __expf(acc[mt][nt][0] * 0.125f) : 0.f;
                float p1 = ((m0w >> (bit + 1)) & 1u) ? __expf(acc[mt][nt][1] * 0.125f) : 0.f;
                float p2 = ((m1w >> bit) & 1u)       ? __expf(acc[mt][nt][2] * 0.125f) : 0.f;
                float p3 = ((m1w >> (bit + 1)) & 1u) ? __expf(acc[mt][nt][3] * 0.125f) : 0.f;
                rsum[mt][0] += p0 + p1;
                rsum[mt][1] += p2 + p3;
                *(__half2*)(p0p + c) = __floats2half2_rn(p0, p1);   // L2-retained
                *(__half2*)(p1p + c) = __floats2half2_rn(p2, p3);
            }
        }
    }

#pragma unroll
    for (int mt = 0; mt < 2; mt++)
#pragma unroll
        for (int hh = 0; hh < 2; hh++) {
            float vv = rsum[mt][hh];
            vv += __shfl_xor_sync(~0u, vv, 1);
            vv += __shfl_xor_sync(~0u, vv, 2);
            if (tig == 0) part[wn * 128 + wm * 32 + mt * 16 + hh * 8 + g] = vv;
        }
    __syncthreads();
    if (tid < 128) invs[tid] = 1.f / (part[tid] + part[128 + tid]);
    __syncthreads();   // fences phase-1 P stores for phase-2 reads

    // ======================= PHASE 2: PV + attn =======================
    auto loadP = [&](int j0, __half* dstP) {
#pragma unroll
        for (int i = 0; i < 8; i++) {
            int id = tid + i * 256;
            int r = id >> 4, c = (id & 15) * 8;
            cp16(&dstP[r * LDP + c], &Pb[(size_t)(q0 + r) * Ln + j0 + c]);
        }
    };
    auto loadV = [&](int j0, __half* dstV) {
#pragma unroll
        for (int i = 0; i < 4; i++) {
            int id = tid + i * 256;
            int d = id >> 4, c = (id & 15) * 8;
            cp16(&dstV[d * LDV + c], &Vt[(size_t)d * Ln + j0 + c]);
        }
    };

    float oacc[2][4][4];
#pragma unroll
    for (int mt = 0; mt < 2; mt++)
#pragma unroll
        for (int nt = 0; nt < 4; nt++)
#pragma unroll
            for (int e = 0; e < 4; e++) oacc[mt][nt][e] = 0.f;

    loadP(0, Ps0);
    loadV(0, Vs0);
    CP_COMMIT();

    for (int jc = 0; jc < 16; jc++) {
        const int j0 = jc * 128;
        CP_WAIT0();
        __syncthreads();
        if (jc + 1 < 16) {
            loadP((jc + 1) * 128, (jc & 1) ? Ps0 : Ps1);
            loadV((jc + 1) * 128, (jc & 1) ? Vs0 : Vs1);
            CP_COMMIT();
        }
        const __half* Pc = (jc & 1) ? Ps1 : Ps0;
        const __half* Vc = (jc & 1) ? Vs1 : Vs0;

        // O += P @ V (unnormalized) -- issued first so tensor pipe starts early
#pragma unroll
        for (int ks = 0; ks < 8; ks++) {
            const int kk = ks * 16;
            unsigned af[2][4], bf[4][2];
#pragma unroll
            for (int mt = 0; mt < 2; mt++)
                ldmA(af[mt], Pc, LDP, wm * 32 + mt * 16, kk, lane);
#pragma unroll
            for (int np = 0; np < 2; np++) {
                unsigned t[4];
                ldmB2(t, Vc, LDV, wn * 32 + np * 16, kk, lane);
                bf[np * 2][0] = t[0]; bf[np * 2][1] = t[1];
                bf[np * 2 + 1][0] = t[2]; bf[np * 2 + 1][1] = t[3];
            }
#pragma unroll
            for (int mt = 0; mt < 2; mt++)
#pragma unroll
                for (int nt = 0; nt < 4; nt++) hmma(oacc[mt][nt], af[mt], bf[nt]);
        }

        // attn = p * inv (fp32, streaming) -- drains behind the mma block
#pragma unroll
        for (int i = 0; i < 8; i++) {
            int id = tid + i * 256;
            int r = id >> 4, c16 = id & 15;
            float inv = invs[r];
            uint4 pv = *(const uint4*)&Pc[r * LDP + c16 * 8];
            const __half2* ph = (const __half2*)&pv;
            float* ap = attn_out + ((size_t)bh * Ln + q0 + r) * Ln + j0 + c16 * 8;
            float2 f0 = __half22float2(ph[0]);
            float2 f1 = __half22float2(ph[1]);
            float2 f2 = __half22float2(ph[2]);
            float2 f3 = __half22float2(ph[3]);
            stcs4(ap,     make_float4(f0.x * inv, f0.y * inv, f1.x * inv, f1.y * inv));
            stcs4(ap + 4, make_float4(f2.x * inv, f2.y * inv, f3.x * inv, f3.y * inv));
        }
        // no trailing barrier: next iteration's top-of-loop __syncthreads()
        // (after CP_WAIT0) already orders this iteration's reads of buffer
        // (jc&1) before iteration jc+2's loads overwrite it.
    }

    float myinv[2][2];
#pragma unroll
    for (int mt = 0; mt < 2; mt++)
#pragma unroll
        for (int hh = 0; hh < 2; hh++)
            myinv[mt][hh] = invs[wm * 32 + mt * 16 + hh * 8 + g];

    __half* Oh = g_oh + (size_t)bh * Ln * 64;
#pragma unroll
    for (int mt = 0; mt < 2; mt++) {
        int rb = wm * 32 + mt * 16;
#pragma unroll
        for (int nt = 0; nt < 4; nt++) {
            int c = wn * 32 + nt * 8 + 2 * tig;
#pragma unroll
            for (int hh = 0; hh < 2; hh++) {
                int r = q0 + rb + hh * 8 + g;
                __half2 o = __floats2half2_rn(oacc[mt][nt][hh * 2 + 0] * myinv[mt][hh],
                                              oacc[mt][nt][hh * 2 + 1] * myinv[mt][hh]);
                *(__half2*)&Oh[(size_t)r * 64 + c] = o;
            }
        }
    }
}

// ---------------------------------------------------------------------------
extern "C" void kernel_launch(void* const* d_in, const int* in_sizes, int n_in,
                              void* d_out, int out_size)
{
    const float* q    = (const float*)d_in[0];
    const float* k    = (const float*)d_in[1];
    const float* v    = (const float*)d_in[2];
    const int*   mask = (const int*)d_in[3];
    const float* Wq   = (const float*)d_in[4];
    const float* bq   = (const float*)d_in[5];
    const float* Wk   = (const float*)d_in[6];
    const float* bk   = (const float*)d_in[7];
    const float* Wv   = (const float*)d_in[8];
    const float* bv   = (const float*)d_in[9];
    const float* Wo   = (const float*)d_in[10];
    const float* bo   = (const float*)d_in[11];

    float* out  = (float*)d_out;                    // [B,L,D]
    float* attn = out + (size_t)BLn * Dn;           // [B,H,L,L]

    pack_x_kernel<<<dim3((BLn * Dn) / 4 / 256, 3), 256>>>(q, k, v);
    pack_w_kernel<<<dim3(32, 32, 4), dim3(32, 8)>>>(Wq, Wk, Wv, Wo);
    pack_mask_kernel<<<(Bn * Ln * Ln) / 256, 256>>>(mask);

    cudaFuncSetAttribute(proj_qkv_kernel, cudaFuncAttributeMaxDynamicSharedMemorySize, PROJ_SMEM_BYTES);
    proj_qkv_kernel<<<dim3(8, 64, 3), 256, PROJ_SMEM_BYTES>>>(bq, bk, bv);

    cudaFuncSetAttribute(attn_fused_kernel, cudaFuncAttributeMaxDynamicSharedMemorySize, ATTN_SMEM_BYTES);
    attn_fused_kernel<<<dim3(Ln / 128, Hn, Bn), 256, ATTN_SMEM_BYTES>>>(attn);

    cudaFuncSetAttribute(out_proj_kernel, cudaFuncAttributeMaxDynamicSharedMemorySize, PROJ_SMEM_BYTES);
    out_proj_kernel<<<dim3(8, 64), 256, PROJ_SMEM_BYTES>>>(bo, out);
}

// round 17
// speedup vs baseline: 1.0651x; 1.0651x over previous
#include <cuda_runtime.h>
#include <cuda_fp16.h>

#define Bn 4
#define Ln 2048
#define Dn 1024
#define Hn 16
#define BLn (Bn*Ln)   // 8192
#define BHn (Bn*Hn)   // 64

__device__ __half g_xh[3][(size_t)BLn*Dn];
__device__ __half g_wt[4][(size_t)Dn*Dn];      // W^T [n][k]
__device__ unsigned g_mbits[(size_t)Bn*Ln*64];
__device__ __half g_qh[(size_t)BHn*Ln*64];
__device__ __half g_kh[(size_t)BHn*Ln*64];
__device__ __half g_vt[(size_t)BHn*64*Ln];     // V^T [bh][d][l]
__device__ __half g_oh[(size_t)BHn*Ln*64];
__device__ __half g_ps[(size_t)BHn*Ln*Ln];     // unnormalized P [bh][l][Ln]

// ---------------------------------------------------------------------------
__device__ __forceinline__ void hmma(float d[4], const unsigned a[4], const unsigned b[2]) {
    asm volatile(
        "mma.sync.aligned.m16n8k16.row.col.f32.f16.f16.f32 "
        "{%0,%1,%2,%3}, {%4,%5,%6,%7}, {%8,%9}, {%0,%1,%2,%3};"
        : "+f"(d[0]), "+f"(d[1]), "+f"(d[2]), "+f"(d[3])
        : "r"(a[0]), "r"(a[1]), "r"(a[2]), "r"(a[3]), "r"(b[0]), "r"(b[1]));
}

__device__ __forceinline__ void ldm4(unsigned r[4], const __half* p) {
    unsigned addr = (unsigned)__cvta_generic_to_shared(p);
    asm volatile("ldmatrix.sync.aligned.m8n8.x4.shared.b16 {%0,%1,%2,%3}, [%4];"
        : "=r"(r[0]), "=r"(r[1]), "=r"(r[2]), "=r"(r[3]) : "r"(addr));
}
__device__ __forceinline__ void ldmA(unsigned r[4], const __half* base, int ldw,
                                     int rb, int kk, int lane) {
    ldm4(r, base + (size_t)(rb + (lane & 15)) * ldw + kk + ((lane >> 4) << 3));
}
__device__ __forceinline__ void ldmB2(unsigned r[4], const __half* base, int ldw,
                                      int nb, int kk, int lane) {
    ldm4(r, base + (size_t)(nb + (lane & 7) + ((lane & 16) >> 1)) * ldw
            + kk + ((lane & 8) ? 8 : 0));
}

__device__ __forceinline__ void cp16(void* s, const void* g) {
    unsigned sa = (unsigned)__cvta_generic_to_shared(s);
    asm volatile("cp.async.cg.shared.global [%0], [%1], 16;" :: "r"(sa), "l"(g));
}
#define CP_COMMIT() asm volatile("cp.async.commit_group;")
#define CP_WAIT0()  asm volatile("cp.async.wait_group 0;")

__device__ __forceinline__ void stcs4(float* p, float4 v) {
    asm volatile("st.global.cs.v4.f32 [%0], {%1,%2,%3,%4};"
        :: "l"(p), "f"(v.x), "f"(v.y), "f"(v.z), "f"(v.w));
}

// ---------------------------------------------------------------------------
// pack kernels
// ---------------------------------------------------------------------------
__global__ __launch_bounds__(256) void pack_x_kernel(
    const float* __restrict__ q, const float* __restrict__ k, const float* __restrict__ v)
{
    int z = blockIdx.y;
    const float* src = (z == 0) ? q : (z == 1) ? k : v;
    __half* dst = g_xh[z];
    size_t i = (size_t)blockIdx.x * 256 + threadIdx.x;
    float4 a = ((const float4*)src)[i];
    ((__half2*)dst)[2 * i]     = __floats2half2_rn(a.x, a.y);
    ((__half2*)dst)[2 * i + 1] = __floats2half2_rn(a.z, a.w);
}

__global__ void pack_w_kernel(
    const float* __restrict__ Wq, const float* __restrict__ Wk,
    const float* __restrict__ Wv, const float* __restrict__ Wo)
{
    __shared__ float s[32][33];
    int z = blockIdx.z;
    const float* W = (z == 0) ? Wq : (z == 1) ? Wk : (z == 2) ? Wv : Wo;
    __half* dst = g_wt[z];
    int k0 = blockIdx.x * 32, n0 = blockIdx.y * 32;
    int tx = threadIdx.x, ty = threadIdx.y;
#pragma unroll
    for (int i = 0; i < 4; i++)
        s[ty + 8 * i][tx] = W[(size_t)(k0 + ty + 8 * i) * 1024 + n0 + tx];
    __syncthreads();
#pragma unroll
    for (int i = 0; i < 4; i++)
        dst[(size_t)(n0 + ty + 8 * i) * 1024 + k0 + tx] = __float2half(s[tx][ty + 8 * i]);
}

__global__ __launch_bounds__(256) void pack_mask_kernel(const int* __restrict__ mask)
{
    size_t i = (size_t)blockIdx.x * 256 + threadIdx.x;
    int m = mask[i];
    unsigned w = __ballot_sync(~0u, m != 0);
    if ((threadIdx.x & 31) == 0) g_mbits[i >> 5] = w;
}

// ---------------------------------------------------------------------------
// QKV projection: BK=64, 2-stage cp.async, ldmatrix; V written transposed.
// (round-12 configuration, verbatim)
// ---------------------------------------------------------------------------
#define LDW 72
#define PROJ_SMEM_BYTES (4 * 128 * LDW * 2)

__global__ __launch_bounds__(256) void proj_qkv_kernel(
    const float* __restrict__ bq, const float* __restrict__ bk, const float* __restrict__ bv)
{
    const int z = blockIdx.z;
    const __half* A  = g_xh[z];
    const __half* Wt = g_wt[z];
    const float* bias = (z == 0) ? bq : (z == 1) ? bk : bv;

    extern __shared__ __half dsm[];
    __half* As = dsm;
    __half* Ws = dsm + 2 * 128 * LDW;

    const int tid  = threadIdx.x;
    const int lane = tid & 31;
    const int warp = tid >> 5;
    const int g    = lane >> 2;
    const int tig  = lane & 3;
    const int wm   = warp & 3;
    const int wn   = warp >> 2;
    const int m0   = blockIdx.y * 128;
    const int n0   = blockIdx.x * 128;

    float acc[2][8][4];
#pragma unroll
    for (int mt = 0; mt < 2; mt++)
#pragma unroll
        for (int nt = 0; nt < 8; nt++)
#pragma unroll
            for (int e = 0; e < 4; e++) acc[mt][nt][e] = 0.f;

    auto loadStage = [&](int kn, int st) {
        __half* Ad = As + st * 128 * LDW;
        __half* Wd = Ws + st * 128 * LDW;
#pragma unroll
        for (int i = 0; i < 4; i++) {
            int id = tid + i * 256;
            int r = id >> 3, c = (id & 7) * 8;
            cp16(&Ad[r * LDW + c], &A[(size_t)(m0 + r) * 1024 + kn + c]);
            cp16(&Wd[r * LDW + c], &Wt[(size_t)(n0 + r) * 1024 + kn + c]);
        }
    };

    loadStage(0, 0);
    CP_COMMIT();

    for (int it = 0; it < 16; it++) {
        CP_WAIT0();
        __syncthreads();
        if (it + 1 < 16) {
            loadStage((it + 1) * 64, (it + 1) & 1);
            CP_COMMIT();
        }
        const __half* Ac = As + (it & 1) * 128 * LDW;
        const __half* Wc = Ws + (it & 1) * 128 * LDW;
#pragma unroll
        for (int ks = 0; ks < 4; ks++) {
            const int kk = ks * 16;
            unsigned af[2][4], bf[8][2];
#pragma unroll
            for (int mt = 0; mt < 2; mt++)
                ldmA(af[mt], Ac, LDW, wm * 32 + mt * 16, kk, lane);
#pragma unroll
            for (int np = 0; np < 4; np++) {
                unsigned t[4];
                ldmB2(t, Wc, LDW, wn * 64 + np * 16, kk, lane);
                bf[np * 2][0] = t[0]; bf[np * 2][1] = t[1];
                bf[np * 2 + 1][0] = t[2]; bf[np * 2 + 1][1] = t[3];
            }
#pragma unroll
            for (int mt = 0; mt < 2; mt++)
#pragma unroll
                for (int nt = 0; nt < 8; nt++) hmma(acc[mt][nt], af[mt], bf[nt]);
        }
        __syncthreads();
    }

    if (z == 2) {
#pragma unroll
        for (int mt = 0; mt < 2; mt++) {
            int rb = wm * 32 + mt * 16;
#pragma unroll
            for (int nt = 0; nt < 8; nt++) {
                int gn = n0 + wn * 64 + nt * 8 + 2 * tig;
                int h = gn >> 6, d = gn & 63;
                float b0v = bias[gn], b1v = bias[gn + 1];
#pragma unroll
                for (int hh = 0; hh < 2; hh++) {
                    int gm = m0 + rb + hh * 8 + g;
                    int bb_ = gm >> 11, l = gm & 2047;
                    __half* vt = g_vt + (size_t)(bb_ * Hn + h) * 64 * Ln;
                    vt[(size_t)d * Ln + l]       = __float2half(acc[mt][nt][hh * 2 + 0] + b0v);
                    vt[(size_t)(d + 1) * Ln + l] = __float2half(acc[mt][nt][hh * 2 + 1] + b1v);
                }
            }
        }
    } else {
        __half* dst = (z == 0) ? g_qh : g_kh;
#pragma unroll
        for (int mt = 0; mt < 2; mt++) {
            int rb = wm * 32 + mt * 16;
#pragma unroll
            for (int nt = 0; nt < 8; nt++) {
                int gn = n0 + wn * 64 + nt * 8 + 2 * tig;
                int h = gn >> 6, d = gn & 63;
                float b0v = bias[gn], b1v = bias[gn + 1];
#pragma unroll
                for (int hh = 0; hh < 2; hh++) {
                    int gm = m0 + rb + hh * 8 + g;
                    int bb_ = gm >> 11, l = gm & 2047;
                    __half2 o = __floats2half2_rn(acc[mt][nt][hh * 2 + 0] + b0v,
                                                  acc[mt][nt][hh * 2 + 1] + b1v);
                    *(__half2*)&dst[(size_t)((bb_ * Hn + h) * Ln + l) * 64 + d] = o;
                }
            }
        }
    }
}

// ---------------------------------------------------------------------------
// Output projection: 64-row m-tiles for wave balance (1024 CTAs vs 512).
// 8 warps as 2m x 4n, warp tile 32x32. BK=64, 2-stage cp.async, ldmatrix.
// ---------------------------------------------------------------------------
#define OUTPROJ_SMEM_BYTES ((2 * 64 + 2 * 128) * LDW * 2)   // 55,296 B

__global__ __launch_bounds__(256) void out_proj_kernel(
    const float* __restrict__ bo, float* __restrict__ out)
{
    const __half* Wt = g_wt[3];
    extern __shared__ __half dsm[];
    __half* As = dsm;                    // [2][64*LDW]
    __half* Ws = dsm + 2 * 64 * LDW;     // [2][128*LDW]

    const int tid  = threadIdx.x;
    const int lane = tid & 31;
    const int warp = tid >> 5;
    const int g    = lane >> 2;
    const int tig  = lane & 3;
    const int wm   = warp & 1;           // 2 m-warps
    const int wn   = warp >> 1;          // 4 n-warps
    const int m0   = blockIdx.y * 64;
    const int n0   = blockIdx.x * 128;

    float acc[2][4][4];
#pragma unroll
    for (int mt = 0; mt < 2; mt++)
#pragma unroll
        for (int nt = 0; nt < 4; nt++)
#pragma unroll
            for (int e = 0; e < 4; e++) acc[mt][nt][e] = 0.f;

    auto loadStage = [&](int kn, int st) {
        __half* Ad = As + st * 64 * LDW;
        __half* Wd = Ws + st * 128 * LDW;
        // A: 64 rows x 64 halves = 512 cp16 (2/thread), gathered from head layout
#pragma unroll
        for (int i = 0; i < 2; i++) {
            int id = tid + i * 256;
            int r = id >> 3, c = (id & 7) * 8;
            int gr = m0 + r;
            int bb_ = gr >> 11, l = gr & 2047;
            int kk = kn + c;
            int h = kk >> 6, dv = kk & 63;
            cp16(&Ad[r * LDW + c], &g_oh[(size_t)((bb_ * Hn + h) * Ln + l) * 64 + dv]);
        }
        // W: 128 rows x 64 halves = 1024 cp16 (4/thread)
#pragma unroll
        for (int i = 0; i < 4; i++) {
            int id = tid + i * 256;
            int r = id >> 3, c = (id & 7) * 8;
            cp16(&Wd[r * LDW + c], &Wt[(size_t)(n0 + r) * 1024 + kn + c]);
        }
    };

    loadStage(0, 0);
    CP_COMMIT();

    for (int it = 0; it < 16; it++) {
        CP_WAIT0();
        __syncthreads();
        if (it + 1 < 16) {
            loadStage((it + 1) * 64, (it + 1) & 1);
            CP_COMMIT();
        }
        const __half* Ac = As + (it & 1) * 64 * LDW;
        const __half* Wc = Ws + (it & 1) * 128 * LDW;
#pragma unroll
        for (int ks = 0; ks < 4; ks++) {
            const int kk = ks * 16;
            unsigned af[2][4], bf[4][2];
#pragma unroll
            for (int mt = 0; mt < 2; mt++)
                ldmA(af[mt], Ac, LDW, wm * 32 + mt * 16, kk, lane);
#pragma unroll
            for (int np = 0; np < 2; np++) {
                unsigned t[4];
                ldmB2(t, Wc, LDW, wn * 32 + np * 16, kk, lane);
                bf[np * 2][0] = t[0]; bf[np * 2][1] = t[1];
                bf[np * 2 + 1][0] = t[2]; bf[np * 2 + 1][1] = t[3];
            }
#pragma unroll
            for (int mt = 0; mt < 2; mt++)
#pragma unroll
                for (int nt = 0; nt < 4; nt++) hmma(acc[mt][nt], af[mt], bf[nt]);
        }
        __syncthreads();
    }
#pragma unroll
    for (int mt = 0; mt < 2; mt++) {
        int rb = wm * 32 + mt * 16;
#pragma unroll
        for (int nt = 0; nt < 4; nt++) {
            int gn = n0 + wn * 32 + nt * 8 + 2 * tig;
            float b0v = bo[gn], b1v = bo[gn + 1];
#pragma unroll
            for (int hh = 0; hh < 2; hh++) {
                int gm = m0 + rb + hh * 8 + g;
                float2 o;
                o.x = acc[mt][nt][hh * 2 + 0] + b0v;
                o.y = acc[mt][nt][hh * 2 + 1] + b1v;
                *(float2*)&out[(size_t)gm * 1024 + gn] = o;
            }
        }
    }
}

// ---------------------------------------------------------------------------
// Fused attention: phase 1 (QK -> P gmem + rowsums), phase 2 (P re-read,
// attn write, PV). (round-12 configuration, verbatim)
// ---------------------------------------------------------------------------
#define LDQ 72
#define LDK 72
#define LDP 136
#define LDV 136
#define UNION_HALVES (2 * 128 * LDP + 2 * 64 * LDV)
#define ATTN_SMEM_BYTES ((256 + 128) * 4 + UNION_HALVES * 2)

__global__ __launch_bounds__(256, 2) void attn_fused_kernel(
    float* __restrict__ attn_out)
{
    extern __shared__ char smraw[];
    float* part = (float*)smraw;            // [2][128]
    float* invs = part + 256;               // [128]
    __half* U   = (__half*)(invs + 128);
    // phase 1 aliases
    __half* Qs  = U;
    __half* Ks0 = U + 128 * LDQ;
    __half* Ks1 = Ks0 + 128 * LDK;
    // phase 2 aliases
    __half* Ps0 = U;
    __half* Ps1 = Ps0 + 128 * LDP;
    __half* Vs0 = Ps1 + 128 * LDP;
    __half* Vs1 = Vs0 + 64 * LDV;

    const int tid  = threadIdx.x;
    const int lane = tid & 31;
    const int warp = tid >> 5;
    const int g    = lane >> 2;
    const int tig  = lane & 3;
    const int wm   = warp & 3;
    const int wn   = warp >> 2;

    const int q0 = blockIdx.x * 128;
    const int h  = blockIdx.y;
    const int b  = blockIdx.z;
    const int bh = b * Hn + h;
    const __half* Qh = g_qh + (size_t)bh * Ln * 64;
    const __half* Kh = g_kh + (size_t)bh * Ln * 64;
    const __half* Vt = g_vt + (size_t)bh * 64 * Ln;
    const unsigned* mb = g_mbits + (size_t)b * Ln * 64;
    __half* Pb = g_ps + (size_t)bh * Ln * Ln;

    auto loadK = [&](int j0, __half* dstK) {
#pragma unroll
        for (int i = 0; i < 4; i++) {
            int id = tid + i * 256;
            int r = id >> 3, c = (id & 7) * 8;
            cp16(&dstK[r * LDK + c], &Kh[(size_t)(j0 + r) * 64 + c]);
        }
    };

    // ======================= PHASE 1: QK -> P, rowsums =======================
#pragma unroll
    for (int i = 0; i < 4; i++) {
        int id = tid + i * 256;
        int r = id >> 3, c8 = id & 7;
        *(uint4*)&Qs[r * LDQ + c8 * 8] = *(const uint4*)&Qh[(size_t)(q0 + r) * 64 + c8 * 8];
    }

    float rsum[2][2] = {{0.f, 0.f}, {0.f, 0.f}};
    loadK(0, Ks0);
    CP_COMMIT();
    __syncthreads();

    for (int jc = 0; jc < 16; jc++) {
        const int j0 = jc * 128;
        CP_WAIT0();
        __syncthreads();
        if (jc + 1 < 16) {
            loadK((jc + 1) * 128, (jc & 1) ? Ks0 : Ks1);
            CP_COMMIT();
        }
        const __half* Kc = (jc & 1) ? Ks1 : Ks0;

        float acc[2][8][4];
#pragma unroll
        for (int mt = 0; mt < 2; mt++)
#pragma unroll
            for (int nt = 0; nt < 8; nt++)
#pragma unroll
                for (int e = 0; e < 4; e++) acc[mt][nt][e] = 0.f;
#pragma unroll
        for (int ks = 0; ks < 4; ks++) {
            const int kk = ks * 16;
            unsigned af[2][4], bf[8][2];
#pragma unroll
            for (int mt = 0; mt < 2; mt++)
                ldmA(af[mt], Qs, LDQ, wm * 32 + mt * 16, kk, lane);
#pragma unroll
            for (int np = 0; np < 4; np++) {
                unsigned t[4];
                ldmB2(t, Kc, LDK, wn * 64 + np * 16, kk, lane);
                bf[np * 2][0] = t[0]; bf[np * 2][1] = t[1];
                bf[np * 2 + 1][0] = t[2]; bf[np * 2 + 1][1] = t[3];
            }
#pragma unroll
            for (int mt = 0; mt < 2; mt++)
#pragma unroll
                for (int nt = 0; nt < 8; nt++) hmma(acc[mt][nt], af[mt], bf[nt]);
        }

#pragma unroll
        for (int mt = 0; mt < 2; mt++) {
            int rb = wm * 32 + mt * 16;
            int r0g = q0 + rb + g;
            int r1g = r0g + 8;
            uint2 w0 = *(const uint2*)&mb[(size_t)r0g * 64 + jc * 4 + wn * 2];
            uint2 w1 = *(const uint2*)&mb[(size_t)r1g * 64 + jc * 4 + wn * 2];
            __half* p0p = Pb + (size_t)r0g * Ln + j0;
            __half* p1p = Pb + (size_t)r1g * Ln + j0;
#pragma unroll
            for (int nt = 0; nt < 8; nt++) {
                int c   = wn * 64 + nt * 8 + 2 * tig;
                int cb  = nt * 8 + 2 * tig;
                int bit = cb & 31;
                unsigned m0w = (cb >> 5) ? w0.y : w0.x;
                unsigned m1w = (cb >> 5) ? w1.y : w1.x;
                float p0 = ((m0w >> bit) & 1u)       ? __expf(acc[mt][nt][0] * 0.125f) : 0.f;
                float p1 = ((m0w >> (bit + 1)) & 1u) ? __expf(acc[mt][nt][1] * 0.125f) : 0.f;
                float p2 = ((m1w >> bit) & 1u)       ? __expf(acc[mt][nt][2] * 0.125f) : 0.f;
                float p3 = ((m1w >> (bit + 1)) & 1u) ? __expf(acc[mt][nt][3] * 0.125f) : 0.f;
                rsum[mt][0] += p0 + p1;
                rsum[mt][1] += p2 + p3;
                *(__half2*)(p0p + c) = __floats2half2_rn(p0, p1);   // L2-retained
                *(__half2*)(p1p + c) = __floats2half2_rn(p2, p3);
            }
        }
    }

#pragma unroll
    for (int mt = 0; mt < 2; mt++)
#pragma unroll
        for (int hh = 0; hh < 2; hh++) {
            float vv = rsum[mt][hh];
            vv += __shfl_xor_sync(~0u, vv, 1);
            vv += __shfl_xor_sync(~0u, vv, 2);
            if (tig == 0) part[wn * 128 + wm * 32 + mt * 16 + hh * 8 + g] = vv;
        }
    __syncthreads();
    if (tid < 128) invs[tid] = 1.f / (part[tid] + part[128 + tid]);
    __syncthreads();   // fences phase-1 P stores for phase-2 reads

    // ======================= PHASE 2: attn + PV =======================
    auto loadP = [&](int j0, __half* dstP) {
#pragma unroll
        for (int i = 0; i < 8; i++) {
            int id = tid + i * 256;
            int r = id >> 4, c = (id & 15) * 8;
            cp16(&dstP[r * LDP + c], &Pb[(size_t)(q0 + r) * Ln + j0 + c]);
        }
    };
    auto loadV = [&](int j0, __half* dstV) {
#pragma unroll
        for (int i = 0; i < 4; i++) {
            int id = tid + i * 256;
            int d = id >> 4, c = (id & 15) * 8;
            cp16(&dstV[d * LDV + c], &Vt[(size_t)d * Ln + j0 + c]);
        }
    };

    float oacc[2][4][4];
#pragma unroll
    for (int mt = 0; mt < 2; mt++)
#pragma unroll
        for (int nt = 0; nt < 4; nt++)
#pragma unroll
            for (int e = 0; e < 4; e++) oacc[mt][nt][e] = 0.f;

    loadP(0, Ps0);
    loadV(0, Vs0);
    CP_COMMIT();

    for (int jc = 0; jc < 16; jc++) {
        const int j0 = jc * 128;
        CP_WAIT0();
        __syncthreads();
        if (jc + 1 < 16) {
            loadP((jc + 1) * 128, (jc & 1) ? Ps0 : Ps1);
            loadV((jc + 1) * 128, (jc & 1) ? Vs0 : Vs1);
            CP_COMMIT();
        }
        const __half* Pc = (jc & 1) ? Ps1 : Ps0;
        const __half* Vc = (jc & 1) ? Vs1 : Vs0;

        // attn = p * inv (fp32, streaming)
#pragma unroll
        for (int i = 0; i < 8; i++) {
            int id = tid + i * 256;
            int r = id >> 4, c16 = id & 15;
            float inv = invs[r];
            uint4 pv = *(const uint4*)&Pc[r * LDP + c16 * 8];
            const __half2* ph = (const __half2*)&pv;
            float* ap = attn_out + ((size_t)bh * Ln + q0 + r) * Ln + j0 + c16 * 8;
            float2 f0 = __half22float2(ph[0]);
            float2 f1 = __half22float2(ph[1]);
            float2 f2 = __half22float2(ph[2]);
            float2 f3 = __half22float2(ph[3]);
            stcs4(ap,     make_float4(f0.x * inv, f0.y * inv, f1.x * inv, f1.y * inv));
            stcs4(ap + 4, make_float4(f2.x * inv, f2.y * inv, f3.x * inv, f3.y * inv));
        }

        // O += P @ V (unnormalized)
#pragma unroll
        for (int ks = 0; ks < 8; ks++) {
            const int kk = ks * 16;
            unsigned af[2][4], bf[4][2];
#pragma unroll
            for (int mt = 0; mt < 2; mt++)
                ldmA(af[mt], Pc, LDP, wm * 32 + mt * 16, kk, lane);
#pragma unroll
            for (int np = 0; np < 2; np++) {
                unsigned t[4];
                ldmB2(t, Vc, LDV, wn * 32 + np * 16, kk, lane);
                bf[np * 2][0] = t[0]; bf[np * 2][1] = t[1];
                bf[np * 2 + 1][0] = t[2]; bf[np * 2 + 1][1] = t[3];
            }
#pragma unroll
            for (int mt = 0; mt < 2; mt++)
#pragma unroll
                for (int nt = 0; nt < 4; nt++) hmma(oacc[mt][nt], af[mt], bf[nt]);
        }
        __syncthreads();
    }

    float myinv[2][2];
#pragma unroll
    for (int mt = 0; mt < 2; mt++)
#pragma unroll
        for (int hh = 0; hh < 2; hh++)
            myinv[mt][hh] = invs[wm * 32 + mt * 16 + hh * 8 + g];

    __half* Oh = g_oh + (size_t)bh * Ln * 64;
#pragma unroll
    for (int mt = 0; mt < 2; mt++) {
        int rb = wm * 32 + mt * 16;
#pragma unroll
        for (int nt = 0; nt < 4; nt++) {
            int c = wn * 32 + nt * 8 + 2 * tig;
#pragma unroll
            for (int hh = 0; hh < 2; hh++) {
                int r = q0 + rb + hh * 8 + g;
                __half2 o = __floats2half2_rn(oacc[mt][nt][hh * 2 + 0] * myinv[mt][hh],
                                              oacc[mt][nt][hh * 2 + 1] * myinv[mt][hh]);
                *(__half2*)&Oh[(size_t)r * 64 + c] = o;
            }
        }
    }
}

// ---------------------------------------------------------------------------
extern "C" void kernel_launch(void* const* d_in, const int* in_sizes, int n_in,
                              void* d_out, int out_size)
{
    const float* q    = (const float*)d_in[0];
    const float* k    = (const float*)d_in[1];
    const float* v    = (const float*)d_in[2];
    const int*   mask = (const int*)d_in[3];
    const float* Wq   = (const float*)d_in[4];
    const float* bq   = (const float*)d_in[5];
    const float* Wk   = (const float*)d_in[6];
    const float* bk   = (const float*)d_in[7];
    const float* Wv   = (const float*)d_in[8];
    const float* bv   = (const float*)d_in[9];
    const float* Wo   = (const float*)d_in[10];
    const float* bo   = (const float*)d_in[11];

    float* out  = (float*)d_out;                    // [B,L,D]
    float* attn = out + (size_t)BLn * Dn;           // [B,H,L,L]

    pack_x_kernel<<<dim3((BLn * Dn) / 4 / 256, 3), 256>>>(q, k, v);
    pack_w_kernel<<<dim3(32, 32, 4), dim3(32, 8)>>>(Wq, Wk, Wv, Wo);
    pack_mask_kernel<<<(Bn * Ln * Ln) / 256, 256>>>(mask);

    cudaFuncSetAttribute(proj_qkv_kernel, cudaFuncAttributeMaxDynamicSharedMemorySize, PROJ_SMEM_BYTES);
    proj_qkv_kernel<<<dim3(8, 64, 3), 256, PROJ_SMEM_BYTES>>>(bq, bk, bv);

    cudaFuncSetAttribute(attn_fused_kernel, cudaFuncAttributeMaxDynamicSharedMemorySize, ATTN_SMEM_BYTES);
    attn_fused_kernel<<<dim3(Ln / 128, Hn, Bn), 256, ATTN_SMEM_BYTES>>>(attn);

    cudaFuncSetAttribute(out_proj_kernel, cudaFuncAttributeMaxDynamicSharedMemorySize, OUTPROJ_SMEM_BYTES);
    out_proj_kernel<<<dim3(8, 128), 256, OUTPROJ_SMEM_BYTES>>>(bo, out);
}